// round 4
// baseline (speedup 1.0000x reference)
#include <cuda_runtime.h>

// Problem constants
#define Bv 64
#define Cv 256
#define Nv 307
#define Tv 12
#define NT (Nv * Tv)   // 3684

// Scratch (device globals: allocation-free rule)
__device__ float g_k[Bv * Cv * Tv];             // pooled k: [B, C, T]
__device__ float g_attT[(size_t)Bv * Cv * Cv];  // softmax(att) TRANSPOSED: [b][d][c]

// ---- f32x2 packed-FMA helpers (Blackwell FFMA2; PTX-only) ----
__device__ __forceinline__ unsigned long long pack_dup_f32(float v) {
    unsigned long long p;
    unsigned int r = __float_as_uint(v);
    asm("mov.b64 %0, {%1, %1};" : "=l"(p) : "r"(r));
    return p;
}
__device__ __forceinline__ void fma_f32x2(unsigned long long& d,
                                          unsigned long long a,
                                          unsigned long long b) {
    asm("fma.rn.f32x2 %0, %1, %2, %0;" : "+l"(d) : "l"(a), "l"(b));
}
__device__ __forceinline__ void unpack_f32x2(unsigned long long p, float& lo, float& hi) {
    unsigned int l, h;
    asm("mov.b64 {%0, %1}, %2;" : "=r"(l), "=r"(h) : "l"(p));
    lo = __uint_as_float(l);
    hi = __uint_as_float(h);
}

// ---------------------------------------------------------------------------
// Stage 1: k[b,c,t] = sum_i alpha[i] * x[b,c,i,t]
// ---------------------------------------------------------------------------
__global__ void pool_kernel(const float* __restrict__ x,
                            const float* __restrict__ alpha) {
    __shared__ float a_sm[Nv];
    __shared__ float red[384];
    const int bc  = blockIdx.x;
    const int tid = threadIdx.x;

    for (int i = tid; i < Nv; i += 384) a_sm[i] = alpha[i];
    __syncthreads();

    const float* xp = x + (size_t)bc * NT;
    float acc = 0.f;
    for (int idx = tid; idx < NT; idx += 384) {
        acc += a_sm[idx / Tv] * xp[idx];   // t = idx % 12 constant per thread
    }
    red[tid] = acc;
    __syncthreads();

    if (tid < Tv) {
        float s = 0.f;
#pragma unroll
        for (int j = 0; j < 32; j++) s += red[tid + j * Tv];
        g_k[bc * Tv + tid] = s;
    }
}

// ---------------------------------------------------------------------------
// Stage 2: att = softmax_d(kW k^T), stored TRANSPOSED g_attT[b][d][c]
// (coalesced stores; direct [k][m] tiles for stage 3)
// ---------------------------------------------------------------------------
__global__ void att_kernel(const float* __restrict__ W) {
    __shared__ float k_sm[Cv * Tv];   // 12 KB
    __shared__ float W_sm[Tv * Tv];
    const int b = blockIdx.x;
    const int c = threadIdx.x;        // 0..255

    for (int i = c; i < Cv * Tv; i += Cv) k_sm[i] = g_k[b * Cv * Tv + i];
    if (c < Tv * Tv) W_sm[c] = W[c];
    __syncthreads();

    float kw[Tv];
#pragma unroll
    for (int t = 0; t < Tv; t++) {
        float s = 0.f;
#pragma unroll
        for (int ss = 0; ss < Tv; ss++) s += k_sm[c * Tv + ss] * W_sm[ss * Tv + t];
        kw[t] = s;
    }

    float m = -1e30f;
    for (int d = 0; d < Cv; d++) {
        float s = 0.f;
#pragma unroll
        for (int t = 0; t < Tv; t++) s += kw[t] * k_sm[d * Tv + t];
        m = fmaxf(m, s);
    }

    float* attT = g_attT + (size_t)b * Cv * Cv;   // [d][c]
    float Z = 0.f;
    for (int d = 0; d < Cv; d++) {
        float s = 0.f;
#pragma unroll
        for (int t = 0; t < Tv; t++) s += kw[t] * k_sm[d * Tv + t];
        float e = expf(s - m);
        attT[d * Cv + c] = e;
        Z += e;
    }

    const float inv = 1.f / Z;
    for (int d = 0; d < Cv; d++) attT[d * Cv + c] *= inv;
}

// ---------------------------------------------------------------------------
// Stage 3: out[b] = att[b] (256x256) @ x[b] (256x3684)
// BM=BN=128, BK=16, 8x8 microtile on FFMA2 (f32x2), 256 threads.
// Double-buffered smem pipeline, single __syncthreads per k-tile.
// ---------------------------------------------------------------------------
#define BM 128
#define BN 128
#define BK 16
#define TM 8
#define TN 8
#define NITER (Cv / BK)   // 16

__global__ __launch_bounds__(256, 2) void mix_kernel(const float* __restrict__ x,
                                                     float* __restrict__ out) {
    __shared__ float As[2][BK][BM];   // att tile [k][m]
    __shared__ float Bs[2][BK][BN];   // x tile [k][n]

    const int b  = blockIdx.z;
    const int m0 = blockIdx.y * BM;
    const int n0 = blockIdx.x * BN;
    const int tid = threadIdx.x;
    const int tx = tid % 16;
    const int ty = tid / 16;

    const float* AT = g_attT + (size_t)b * Cv * Cv;  // [k=256][m=256]
    const float* Bx = x + (size_t)b * Cv * NT;       // [256][3684]
    float*       O  = out + (size_t)b * Cv * NT;

    unsigned long long acc[TM][TN / 2] = {};   // 8 rows x 4 packed pairs

    const int krow = tid / 32;          // 0..7 (+8 on 2nd pass)
    const int mcol = (tid % 32) * 4;    // 0..124
    const int gcol = n0 + mcol;         // global B column
    const bool bok = (gcol < NT);       // NT % 4 == 0: float4 predication safe

    // ---- prologue: tile 0 straight into buffer 0 ----
#pragma unroll
    for (int p = 0; p < 2; p++) {
        int kk = krow + p * 8;
        *reinterpret_cast<float4*>(&As[0][kk][mcol]) =
            *reinterpret_cast<const float4*>(AT + (size_t)kk * Cv + m0 + mcol);
        float4 v = make_float4(0.f, 0.f, 0.f, 0.f);
        if (bok) v = *reinterpret_cast<const float4*>(Bx + (size_t)kk * NT + gcol);
        *reinterpret_cast<float4*>(&Bs[0][kk][mcol]) = v;
    }
    __syncthreads();

#pragma unroll 1
    for (int it = 0; it < NITER; it++) {
        const int cur = it & 1;

        // ---- issue next tile's global loads (latency hides behind compute) ----
        float4 a_st[2], b_st[2];
        const bool has_next = (it + 1 < NITER);
        if (has_next) {
            const int k0n = (it + 1) * BK;
#pragma unroll
            for (int p = 0; p < 2; p++) {
                int kk = k0n + krow + p * 8;
                a_st[p] = *reinterpret_cast<const float4*>(AT + (size_t)kk * Cv + m0 + mcol);
                float4 v = make_float4(0.f, 0.f, 0.f, 0.f);
                if (bok) v = *reinterpret_cast<const float4*>(Bx + (size_t)kk * NT + gcol);
                b_st[p] = v;
            }
        }

        // ---- compute on buffer `cur` ----
#pragma unroll
        for (int k = 0; k < BK; k++) {
            const ulonglong2 rb01 =
                *reinterpret_cast<const ulonglong2*>(&Bs[cur][k][tx * TN]);
            const ulonglong2 rb23 =
                *reinterpret_cast<const ulonglong2*>(&Bs[cur][k][tx * TN + 4]);
            unsigned long long rb[TN / 2] = {rb01.x, rb01.y, rb23.x, rb23.y};

            const float4 a03 = *reinterpret_cast<const float4*>(&As[cur][k][ty * TM]);
            const float4 a47 = *reinterpret_cast<const float4*>(&As[cur][k][ty * TM + 4]);
            const float av[TM] = {a03.x, a03.y, a03.z, a03.w,
                                  a47.x, a47.y, a47.z, a47.w};
#pragma unroll
            for (int i = 0; i < TM; i++) {
                unsigned long long ra = pack_dup_f32(av[i]);
#pragma unroll
                for (int j = 0; j < TN / 2; j++)
                    fma_f32x2(acc[i][j], ra, rb[j]);
            }
        }

        // ---- stage next tile into the other buffer, one sync ----
        // Safe: the sync at end of iter it-1 guaranteed every warp finished
        // computing on buffer cur^1 before we overwrite it here.
        if (has_next) {
            const int nxt = cur ^ 1;
#pragma unroll
            for (int p = 0; p < 2; p++) {
                int kk = krow + p * 8;
                *reinterpret_cast<float4*>(&As[nxt][kk][mcol]) = a_st[p];
                *reinterpret_cast<float4*>(&Bs[nxt][kk][mcol]) = b_st[p];
            }
            __syncthreads();
        }
    }

    // ---- epilogue: 8x8 per thread; per-float4 column predication ----
#pragma unroll
    for (int i = 0; i < TM; i++) {
        int row = m0 + ty * TM + i;
#pragma unroll
        for (int j4 = 0; j4 < 2; j4++) {
            int col = n0 + tx * TN + j4 * 4;
            if (col < NT) {
                float v0, v1, v2, v3;
                unpack_f32x2(acc[i][j4 * 2 + 0], v0, v1);
                unpack_f32x2(acc[i][j4 * 2 + 1], v2, v3);
                *reinterpret_cast<float4*>(O + (size_t)row * NT + col) =
                    make_float4(v0, v1, v2, v3);
            }
        }
    }
}

// ---------------------------------------------------------------------------
extern "C" void kernel_launch(void* const* d_in, const int* in_sizes, int n_in,
                              void* d_out, int out_size) {
    const float* x     = (const float*)d_in[0];  // [64,256,307,12]
    const float* W     = (const float*)d_in[1];  // [12,12]
    const float* alpha = (const float*)d_in[2];  // [307]
    float*       out   = (float*)d_out;          // [64,256,307,12]

    pool_kernel<<<Bv * Cv, 384>>>(x, alpha);
    att_kernel<<<Bv, Cv>>>(W);

    dim3 grid((NT + BN - 1) / BN, Cv / BM, Bv);  // (29, 2, 64)
    mix_kernel<<<grid, 256>>>(x, out);
}